// round 7
// baseline (speedup 1.0000x reference)
#include <cuda_runtime.h>
#include <math.h>

// Problem constants
#define D_    32
#define H_    128
#define B_    64
#define T_    256
#define NSTEP 255
#define TOUT  252
#define QKC   264          // 256 q/k cols + 4 vg cols + 4 pad
#define SCALE_ATTN 0.17677669529663688f
#define LOG2E_F 1.4426950408889634f

typedef unsigned long long u64;

// ---------------- device scratch ----------------
__device__ float d_Wcat2[D_ * H_ * H_ * 4];               // [d][k][h][gate j,i,f,o]
__device__ float d_Ucat2[D_ * H_ * 4];                    // [d][h][gate]
__device__ float d_Bcat2[D_ * H_ * 4];                    // [d][h][gate]
__device__ float d_qkT2[H_ * QKC];                        // [m][c]
__device__ float d_htraj[(size_t)NSTEP * D_ * B_ * H_];   // [t][d][b][h]
__device__ float d_qkbuf[(size_t)TOUT * D_ * B_ * QKC];   // [tt][d][b][c]

// ---------------- fast math helpers ----------------
__device__ __forceinline__ float fexp2a(float x) {
    float r; asm("ex2.approx.ftz.f32 %0, %1;" : "=f"(r) : "f"(x)); return r;
}
__device__ __forceinline__ float frcpa(float x) {
    float r; asm("rcp.approx.ftz.f32 %0, %1;" : "=f"(r) : "f"(x)); return r;
}
__device__ __forceinline__ float fsigmoid(float x) {
    return frcpa(1.f + fexp2a(-x * LOG2E_F));
}
__device__ __forceinline__ float ftanh(float x) {
    return fmaf(-2.f, frcpa(1.f + fexp2a(x * (2.f * LOG2E_F))), 1.f);
}
__device__ __forceinline__ void ffma2(u64& d, u64 a, u64 b) {
    asm("fma.rn.f32x2 %0, %1, %2, %0;" : "+l"(d) : "l"(a), "l"(b));
}
__device__ __forceinline__ u64 pack2f(float lo, float hi) {
    u64 r; asm("mov.b64 %0, {%1, %2};" : "=l"(r) : "f"(lo), "f"(hi)); return r;
}
__device__ __forceinline__ void unpack2(u64 v, float& lo, float& hi) {
    asm("mov.b64 {%0, %1}, %2;" : "=f"(lo), "=f"(hi) : "l"(v));
}
// 16B global load producing two u64 operands directly (no packing movs)
__device__ __forceinline__ void ldg_v2b64(const float* p, u64& a, u64& b) {
    asm("ld.global.nc.v2.b64 {%0, %1}, [%2];" : "=l"(a), "=l"(b) : "l"(p));
}

// ---------------- prep kernels ----------------
__global__ void prep_wcat2(const float* __restrict__ Wj, const float* __restrict__ Wi,
                           const float* __restrict__ Wf, const float* __restrict__ Wo) {
    int idx = blockIdx.x * 256 + threadIdx.x;            // total 32*128*128*4
    if (idx >= D_ * H_ * H_ * 4) return;
    int g = idx & 3, h = (idx >> 2) & 127, k = (idx >> 9) & 127, d = idx >> 16;
    const float* W = (g == 0) ? Wj : (g == 1) ? Wi : (g == 2) ? Wf : Wo;
    d_Wcat2[idx] = W[(d * H_ + k) * H_ + h];
}

__global__ void prep_ub2(const float* __restrict__ Uj, const float* __restrict__ Ui,
                         const float* __restrict__ Uf, const float* __restrict__ Uo,
                         const float* __restrict__ Bj, const float* __restrict__ Bi,
                         const float* __restrict__ Bf, const float* __restrict__ Bo) {
    int idx = blockIdx.x * 256 + threadIdx.x;            // total 32*128*4
    if (idx >= D_ * H_ * 4) return;
    int g = idx & 3, h = (idx >> 2) & 127, d = idx >> 9;
    const float* U = (g == 0) ? Uj : (g == 1) ? Ui : (g == 2) ? Uf : Uo;
    const float* Bp = (g == 0) ? Bj : (g == 1) ? Bi : (g == 2) ? Bf : Bo;
    d_Ucat2[idx] = U[d * H_ + h];
    d_Bcat2[idx] = Bp[d * H_ + h];
}

__global__ void prep_attn(const float* __restrict__ qkv_w, const float* __restrict__ out_w,
                          const float* __restrict__ h_proj_w, const float* __restrict__ w_p) {
    __shared__ float g_s[128];
    __shared__ float g2_s[128];
    int tid = threadIdx.x;  // = m
    float acc = 0.f;
    for (int n = 0; n < 128; n++) acc += h_proj_w[n * 128 + tid] * w_p[n];
    g_s[tid] = acc;
    __syncthreads();
    acc = 0.f;
    for (int hh = 0; hh < 128; hh++) acc += out_w[hh * 128 + tid] * g_s[hh];
    g2_s[tid] = acc;
    __syncthreads();
    for (int c = 0; c < 256; c++) d_qkT2[tid * QKC + c] = qkv_w[c * 128 + tid];
    for (int head = 0; head < 4; head++) {
        float a = 0.f;
        for (int hd = 0; hd < 32; hd++)
            a += qkv_w[(256 + head * 32 + hd) * 128 + tid] * g2_s[head * 32 + hd];
        d_qkT2[tid * QKC + 256 + head] = a;
    }
    for (int c = 260; c < QKC; c++) d_qkT2[tid * QKC + c] = 0.f;
}

// ---------------- phase 1: 255-step recurrence ----------------
// 128 CTAs = 32 d * 4 batch-tiles of 16. 512 threads: h = tid&127, bq = tid>>7.
// f32x2 lanes = gate-pairs (j,i)/(f,o): weights load as v2.b64 (zero packing movs);
// h state stored DUPLICATED (h,h) in smem so it is a ready-made f32x2 operand.
__global__ __launch_bounds__(512) void phase1(const float* __restrict__ x) {
    __shared__ __align__(16) float hT[2][H_ * 32];   // [buf][k][16 batches * 2 dup]
    __shared__ float xs[2][16];

    int d  = blockIdx.x & 31;
    int bt = blockIdx.x >> 5;
    int b0 = bt * 16;
    int tid = threadIdx.x;
    int h  = tid & 127;
    int bq = tid >> 7;           // 0..3 -> local batches bq*4 .. bq*4+3

    for (int i = tid; i < H_ * 32; i += 512) hT[0][i] = 0.f;
    if (tid < 16) xs[0][tid] = x[((b0 + tid) * T_ + 0) * D_ + d];

    const float* Wd = d_Wcat2 + (size_t)d * H_ * H_ * 4 + h * 4;   // + k*512 per k
    float4 u4 = *(const float4*)&d_Ucat2[(d * H_ + h) * 4];
    float4 bias4 = *(const float4*)&d_Bcat2[(d * H_ + h) * 4];

    float cc[4] = {0.f, 0.f, 0.f, 0.f};

    for (int t = 0; t < NSTEP; t++) {
        int cur = t & 1, nxt = cur ^ 1;
        __syncthreads();   // hT[cur], xs[cur] ready

        u64 aji[4] = {0ull, 0ull, 0ull, 0ull};   // lanes (pre_j, pre_i) per batch
        u64 afo[4] = {0ull, 0ull, 0ull, 0ull};   // lanes (pre_f, pre_o) per batch

        const float* hb = &hT[cur][bq * 8];
#pragma unroll 8
        for (int k = 0; k < H_; k++) {
            u64 wji, wfo;
            ldg_v2b64(Wd + k * 512, wji, wfo);
            ulonglong2 h01 = *(const ulonglong2*)&hb[k * 32];       // (b0,b0),(b1,b1)
            ulonglong2 h23 = *(const ulonglong2*)&hb[k * 32 + 4];   // (b2,b2),(b3,b3)
            ffma2(aji[0], h01.x, wji);  ffma2(afo[0], h01.x, wfo);
            ffma2(aji[1], h01.y, wji);  ffma2(afo[1], h01.y, wfo);
            ffma2(aji[2], h23.x, wji);  ffma2(afo[2], h23.x, wfo);
            ffma2(aji[3], h23.y, wji);  ffma2(afo[3], h23.y, wfo);
        }

        size_t base = (((size_t)t * D_ + d) * B_ + (b0 + bq * 4)) * H_ + h;
#pragma unroll
        for (int b = 0; b < 4; b++) {
            float pj, pi, pf, po;
            unpack2(aji[b], pj, pi);
            unpack2(afo[b], pf, po);
            float xv = xs[cur][bq * 4 + b];
            float jj = ftanh(fmaf(xv, u4.x, pj + bias4.x));
            float ii = fsigmoid(fmaf(xv, u4.y, pi + bias4.y));
            float ff = fsigmoid(fmaf(xv, u4.z, pf + bias4.z));
            float oo = fsigmoid(fmaf(xv, u4.w, po + bias4.w));
            cc[b] = fmaf(cc[b], ff, ii * jj);
            float hv = oo * ftanh(cc[b]);
            // duplicated write (f32x2-ready operand for next step)
            hT[nxt][h * 32 + bq * 8 + 2 * b]     = hv;
            hT[nxt][h * 32 + bq * 8 + 2 * b + 1] = hv;
            d_htraj[base + (size_t)b * H_] = hv;
        }
        if (tid < 16 && t + 1 < NSTEP) xs[nxt][tid] = x[((b0 + tid) * T_ + (t + 1)) * D_ + d];
    }
}

// ---------------- phase 2a: batched q/k/vg projection ----------------
// Grid (2 bhalf, 32 d, 252 tt), 288 threads. f32x2 lanes = column-pairs:
// weights load as v2.b64 directly; h rows duplicated in smem (stride 68).
#define HS  68
__global__ __launch_bounds__(288) void phase2a() {
    __shared__ __align__(16) float hsT[128 * HS];  // [m][32 rows * 2 dup], stride 68

    int b0 = blockIdx.x * 32;
    int d  = blockIdx.y;
    int tt = blockIdx.z;
    int t  = tt + 3;

    const float* src = d_htraj + (((size_t)t * D_ + d) * B_ + b0) * H_;
    for (int i = threadIdx.x; i < 32 * 128; i += 288) {
        int r = i >> 7, hh = i & 127;
        float v = src[r * 128 + hh];
        hsT[hh * HS + r * 2]     = v;
        hsT[hh * HS + r * 2 + 1] = v;
    }
    __syncthreads();

    int cg = threadIdx.x >> 2;       // 0..71, cols cg*4..cg*4+3
    int rg = threadIdx.x & 3;        // rows rg*8..rg*8+7
    if (cg < 66) {
        int c0 = cg * 4;
        u64 acc[16];                 // [cp*8 + row]: cp0=(c0,c1), cp1=(c2,c3)
#pragma unroll
        for (int i = 0; i < 16; i++) acc[i] = 0ull;

        const float* hb = &hsT[rg * 16];
        const float* wp = &d_qkT2[c0];
#pragma unroll 4
        for (int k = 0; k < H_; k++) {
            u64 w01, w23;
            ldg_v2b64(wp + k * QKC, w01, w23);
            const ulonglong2* hp = (const ulonglong2*)&hb[k * HS];
            ulonglong2 p0 = hp[0], p1 = hp[1], p2 = hp[2], p3 = hp[3];
            ffma2(acc[0], p0.x, w01);  ffma2(acc[8],  p0.x, w23);
            ffma2(acc[1], p0.y, w01);  ffma2(acc[9],  p0.y, w23);
            ffma2(acc[2], p1.x, w01);  ffma2(acc[10], p1.x, w23);
            ffma2(acc[3], p1.y, w01);  ffma2(acc[11], p1.y, w23);
            ffma2(acc[4], p2.x, w01);  ffma2(acc[12], p2.x, w23);
            ffma2(acc[5], p2.y, w01);  ffma2(acc[13], p2.y, w23);
            ffma2(acc[6], p3.x, w01);  ffma2(acc[14], p3.x, w23);
            ffma2(acc[7], p3.y, w01);  ffma2(acc[15], p3.y, w23);
        }

        float* dst = d_qkbuf + (((size_t)tt * D_ + d) * B_ + b0 + rg * 8) * QKC;
#pragma unroll
        for (int r = 0; r < 8; r++) {
            float v0, v1, v2, v3;
            unpack2(acc[r],     v0, v1);
            unpack2(acc[8 + r], v2, v3);
            *(float4*)&dst[(size_t)r * QKC + c0] = make_float4(v0, v1, v2, v3);
        }
    }
}

// ---------------- phase 2b: scores + softmax + threshold + prediction ----------------
__global__ __launch_bounds__(128) void phase2b(const float* __restrict__ b_p,
                                               float* __restrict__ out) {
    __shared__ __align__(16) float qk[32 * 266];
    __shared__ float wsum[4];

    int b  = blockIdx.x;
    int tt = blockIdx.y;

    const float* src = d_qkbuf + (((size_t)tt * D_) * B_ + b) * QKC;
    for (int d = 0; d < 32; d++) {
        const float* row = src + (size_t)d * B_ * QKC;
        for (int cc = threadIdx.x; cc < QKC; cc += 128) qk[d * 266 + cc] = row[cc];
    }
    __syncthreads();

    int head = threadIdx.x >> 5, j = threadIdx.x & 31;

    u64 kk[16];
    const float* krow = &qk[j * 266 + 128 + head * 32];
#pragma unroll
    for (int i2 = 0; i2 < 16; i2++) {
        float2 f = *(const float2*)&krow[2 * i2];
        kk[i2] = pack2f(f.x, f.y);
    }
    float vgj = qk[j * 266 + 256 + head];

    float acc = 0.f;
    for (int i = 0; i < 32; i++) {
        const float2* qrow = (const float2*)&qk[i * 266 + head * 32];
        u64 sacc = 0ull;
#pragma unroll
        for (int i2 = 0; i2 < 16; i2++) {
            float2 f = qrow[i2];
            ffma2(sacc, pack2f(f.x, f.y), kk[i2]);
        }
        float lo, hi;
        unpack2(sacc, lo, hi);
        float s = (lo + hi) * SCALE_ATTN;

        float m = s;
#pragma unroll
        for (int off = 16; off; off >>= 1) m = fmaxf(m, __shfl_xor_sync(0xffffffffu, m, off));
        float e = fexp2a((s - m) * LOG2E_F);
        float ssum = e;
#pragma unroll
        for (int off = 16; off; off >>= 1) ssum += __shfl_xor_sync(0xffffffffu, ssum, off);
        float p = e * frcpa(ssum);
        float contrib = (p >= 0.01f) ? p * vgj : 0.f;
#pragma unroll
        for (int off = 16; off; off >>= 1) contrib += __shfl_xor_sync(0xffffffffu, contrib, off);
        acc += contrib;
    }
    if (j == 0) wsum[head] = acc;
    __syncthreads();
    if (threadIdx.x == 0)
        out[b * TOUT + tt] = (wsum[0] + wsum[1] + wsum[2] + wsum[3]) * (1.f / 32.f) + b_p[0];
}

// ---------------- launch ----------------
extern "C" void kernel_launch(void* const* d_in, const int* in_sizes, int n_in,
                              void* d_out, int out_size) {
    const float* x   = (const float*)d_in[0];
    const float* Uj  = (const float*)d_in[1];
    const float* Ui  = (const float*)d_in[2];
    const float* Uf  = (const float*)d_in[3];
    const float* Uo  = (const float*)d_in[4];
    const float* Wj  = (const float*)d_in[5];
    const float* Wi  = (const float*)d_in[6];
    const float* Wf  = (const float*)d_in[7];
    const float* Wo  = (const float*)d_in[8];
    const float* Bj  = (const float*)d_in[9];
    const float* Bi  = (const float*)d_in[10];
    const float* Bf  = (const float*)d_in[11];
    const float* Bo  = (const float*)d_in[12];
    // d_in[13..24] dead code
    const float* qkv_w    = (const float*)d_in[25];
    const float* out_w    = (const float*)d_in[26];
    const float* h_proj_w = (const float*)d_in[27];
    const float* w_p      = (const float*)d_in[28];
    const float* b_p      = (const float*)d_in[29];
    float* out = (float*)d_out;

    prep_wcat2<<<(D_ * H_ * H_ * 4 + 255) / 256, 256>>>(Wj, Wi, Wf, Wo);
    prep_ub2<<<(D_ * H_ * 4 + 255) / 256, 256>>>(Uj, Ui, Uf, Uo, Bj, Bi, Bf, Bo);
    prep_attn<<<1, 128>>>(qkv_w, out_w, h_proj_w, w_p);

    phase1<<<128, 512>>>(x);

    dim3 g2a(2, 32, 252);
    phase2a<<<g2a, 288>>>();

    dim3 g2b(B_, TOUT);
    phase2b<<<g2b, 128>>>(b_p, out);
}

// round 8
// speedup vs baseline: 2.1013x; 2.1013x over previous
#include <cuda_runtime.h>
#include <math.h>

// Problem constants
#define D_    32
#define H_    128
#define B_    64
#define T_    256
#define NSTEP 255
#define TOUT  252
#define NG    512          // 4 gates * 128
#define QKC   264          // 256 q/k cols + 4 vg cols + 4 pad
#define KREG  64           // weight k-slices kept in registers
#define KSM   64           // weight k-slices kept in shared memory
#define HTS   20           // hT row stride (floats), 16B-aligned, conflict-reducing
#define SCALE_ATTN 0.17677669529663688f
#define LOG2E_F 1.4426950408889634f

typedef unsigned long long u64;

// ---------------- device scratch ----------------
__device__ float d_Wcat[D_ * H_ * NG];                    // [d][k][n], n = gate*128+h
__device__ float d_Ucat[D_ * NG];                         // [d][n]
__device__ float d_Bcat[D_ * NG];                         // [d][n]
__device__ float d_qkT2[H_ * QKC];                        // [m][c]
__device__ float d_htraj[(size_t)NSTEP * D_ * B_ * H_];   // [t][d][b][h]
__device__ float d_qkbuf[(size_t)TOUT * D_ * B_ * QKC];   // [tt][d][b][c]

// ---------------- fast math helpers ----------------
__device__ __forceinline__ float fexp2a(float x) {
    float r; asm("ex2.approx.ftz.f32 %0, %1;" : "=f"(r) : "f"(x)); return r;
}
__device__ __forceinline__ float frcpa(float x) {
    float r; asm("rcp.approx.ftz.f32 %0, %1;" : "=f"(r) : "f"(x)); return r;
}
__device__ __forceinline__ float fsigmoid(float x) {
    return frcpa(1.f + fexp2a(-x * LOG2E_F));
}
__device__ __forceinline__ float ftanh(float x) {
    return fmaf(-2.f, frcpa(1.f + fexp2a(x * (2.f * LOG2E_F))), 1.f);
}
__device__ __forceinline__ void ffma2(u64& d, u64 a, u64 b) {
    asm("fma.rn.f32x2 %0, %1, %2, %0;" : "+l"(d) : "l"(a), "l"(b));
}
__device__ __forceinline__ u64 pack2(float w) {
    u64 r; asm("mov.b64 %0, {%1, %1};" : "=l"(r) : "f"(w)); return r;
}
__device__ __forceinline__ u64 pack2f(float lo, float hi) {
    u64 r; asm("mov.b64 %0, {%1, %2};" : "=l"(r) : "f"(lo), "f"(hi)); return r;
}
__device__ __forceinline__ void unpack2(u64 v, float& lo, float& hi) {
    asm("mov.b64 {%0, %1}, %2;" : "=f"(lo), "=f"(hi) : "l"(v));
}

// ---------------- prep kernels ----------------
__global__ void prep_wcat(const float* __restrict__ Wj, const float* __restrict__ Wi,
                          const float* __restrict__ Wf, const float* __restrict__ Wo) {
    int idx = blockIdx.x * 256 + threadIdx.x;          // total 32*128*512
    if (idx >= D_ * H_ * NG) return;
    int n = idx & 511, k = (idx >> 9) & 127, d = idx >> 16;
    int g = n >> 7, h = n & 127;
    const float* W = (g == 0) ? Wj : (g == 1) ? Wi : (g == 2) ? Wf : Wo;
    d_Wcat[idx] = W[(d * H_ + k) * H_ + h];
}

__global__ void prep_ub(const float* __restrict__ Uj, const float* __restrict__ Ui,
                        const float* __restrict__ Uf, const float* __restrict__ Uo,
                        const float* __restrict__ Bj, const float* __restrict__ Bi,
                        const float* __restrict__ Bf, const float* __restrict__ Bo) {
    int idx = blockIdx.x * 256 + threadIdx.x;          // total 32*512
    if (idx >= D_ * NG) return;
    int n = idx & 511, d = idx >> 9;
    int g = n >> 7, h = n & 127;
    const float* U = (g == 0) ? Uj : (g == 1) ? Ui : (g == 2) ? Uf : Uo;
    const float* Bp = (g == 0) ? Bj : (g == 1) ? Bi : (g == 2) ? Bf : Bo;
    d_Ucat[idx] = U[d * H_ + h];
    d_Bcat[idx] = Bp[d * H_ + h];
}

__global__ void prep_attn(const float* __restrict__ qkv_w, const float* __restrict__ out_w,
                          const float* __restrict__ h_proj_w, const float* __restrict__ w_p) {
    __shared__ float g_s[128];
    __shared__ float g2_s[128];
    int tid = threadIdx.x;  // = m
    float acc = 0.f;
    for (int n = 0; n < 128; n++) acc += h_proj_w[n * 128 + tid] * w_p[n];
    g_s[tid] = acc;
    __syncthreads();
    acc = 0.f;
    for (int hh = 0; hh < 128; hh++) acc += out_w[hh * 128 + tid] * g_s[hh];
    g2_s[tid] = acc;
    __syncthreads();
    for (int c = 0; c < 256; c++) d_qkT2[tid * QKC + c] = qkv_w[c * 128 + tid];
    for (int head = 0; head < 4; head++) {
        float a = 0.f;
        for (int hd = 0; hd < 32; hd++)
            a += qkv_w[(256 + head * 32 + hd) * 128 + tid] * g2_s[head * 32 + hd];
        d_qkT2[tid * QKC + 256 + head] = a;
    }
    for (int c = 260; c < QKC; c++) d_qkT2[tid * QKC + c] = 0.f;
}

// ---------------- phase 1: 255-step recurrence, weights resident in regs+smem ----------------
// 128 CTAs = 32 d * 4 batch-tiles of 16. 512 threads = one gate-column n each.
// Weights w[k][n]: k<64 in per-thread registers, k>=64 in smem. NO global weight
// traffic inside the time loop. c-state in registers (4 cells per thread).
// Dynamic smem (floats):
//   wsm   [0, 32768)           : [kk][512]   (k = 64+kk)          128 KB
//   hT    [32768, +2*128*HTS)  : [buf][k][HTS] (16 batches used)   20 KB
//   pre   [.., +8192)          : [16][512]                         32 KB
//   xs    [.., +16)
#define SM1_WSM  0
#define SM1_HT   (KSM * NG)
#define SM1_PRE  (SM1_HT + 2 * H_ * HTS)
#define SM1_XS   (SM1_PRE + 16 * NG)
#define SM1_TOTAL (SM1_XS + 16)
__global__ __launch_bounds__(512) void phase1(const float* __restrict__ x) {
    extern __shared__ __align__(16) float smem1[];
    float* wsm = smem1 + SM1_WSM;
    float* hT  = smem1 + SM1_HT;
    float* pre = smem1 + SM1_PRE;
    float* xs  = smem1 + SM1_XS;

    int d  = blockIdx.x & 31;
    int bt = blockIdx.x >> 5;
    int b0 = bt * 16;
    int n  = threadIdx.x;

    const float* Wd = d_Wcat + (size_t)d * H_ * NG;

    // load resident weights: k < KREG into registers, rest into smem (once)
    float wreg[KREG];
#pragma unroll
    for (int k = 0; k < KREG; k++) wreg[k] = Wd[k * NG + n];
    for (int kk = 0; kk < KSM; kk++) wsm[kk * NG + n] = Wd[(KREG + kk) * NG + n];

    // init h state + c state
    for (int i = n; i < 2 * H_ * HTS; i += 512) hT[i] = 0.f;
    float creg[4] = {0.f, 0.f, 0.f, 0.f};

    float u    = d_Ucat[d * NG + n];
    float bias = d_Bcat[d * NG + n];

    for (int t = 0; t < NSTEP; t++) {
        int cur = t & 1, nxt = cur ^ 1;
        if (n < 16) xs[n] = x[((b0 + n) * T_ + t) * D_ + d];
        __syncthreads();   // hT[cur] (prev epilogue) + xs ready; wsm ready (t=0)

        u64 acc[8];
#pragma unroll
        for (int i = 0; i < 8; i++) acc[i] = 0ull;

        const float* hc = &hT[cur * H_ * HTS];
#pragma unroll
        for (int k = 0; k < KREG; k++) {
            u64 ww = pack2(wreg[k]);
            const ulonglong2* hp = (const ulonglong2*)&hc[k * HTS];
            ulonglong2 p0 = hp[0], p1 = hp[1], p2 = hp[2], p3 = hp[3];
            ffma2(acc[0], p0.x, ww);  ffma2(acc[1], p0.y, ww);
            ffma2(acc[2], p1.x, ww);  ffma2(acc[3], p1.y, ww);
            ffma2(acc[4], p2.x, ww);  ffma2(acc[5], p2.y, ww);
            ffma2(acc[6], p3.x, ww);  ffma2(acc[7], p3.y, ww);
        }
#pragma unroll
        for (int kk = 0; kk < KSM; kk++) {
            u64 ww = pack2(wsm[kk * NG + n]);
            const ulonglong2* hp = (const ulonglong2*)&hc[(KREG + kk) * HTS];
            ulonglong2 p0 = hp[0], p1 = hp[1], p2 = hp[2], p3 = hp[3];
            ffma2(acc[0], p0.x, ww);  ffma2(acc[1], p0.y, ww);
            ffma2(acc[2], p1.x, ww);  ffma2(acc[3], p1.y, ww);
            ffma2(acc[4], p2.x, ww);  ffma2(acc[5], p2.y, ww);
            ffma2(acc[6], p3.x, ww);  ffma2(acc[7], p3.y, ww);
        }

        // pre-activations (+ x*u + bias) -> exchange buffer
#pragma unroll
        for (int i = 0; i < 8; i++) {
            float lo, hi;
            unpack2(acc[i], lo, hi);
            pre[(2 * i) * NG + n]     = fmaf(xs[2 * i], u, lo + bias);
            pre[(2 * i + 1) * NG + n] = fmaf(xs[2 * i + 1], u, hi + bias);
        }
        __syncthreads();

        // 2048 (bb,h) cells, 4 per thread; c in registers (fixed cell ownership)
#pragma unroll
        for (int i = 0; i < 4; i++) {
            int cell = n + i * 512;
            int bb = cell >> 7, h = cell & 127;
            float pj = pre[bb * NG + h];
            float pi = pre[bb * NG + 128 + h];
            float pf = pre[bb * NG + 256 + h];
            float po = pre[bb * NG + 384 + h];
            float jj = ftanh(pj);
            float ii = fsigmoid(pi);
            float ff = fsigmoid(pf);
            float oo = fsigmoid(po);
            creg[i] = fmaf(creg[i], ff, ii * jj);
            float hv = oo * ftanh(creg[i]);
            hT[nxt * H_ * HTS + h * HTS + bb] = hv;
            d_htraj[(((size_t)t * D_ + d) * B_ + (b0 + bb)) * H_ + h] = hv;
        }
    }
}

// ---------------- phase 2a: batched q/k/vg projection (proven R4/R5 version) ----------------
__global__ __launch_bounds__(288) void phase2a() {
    __shared__ __align__(16) float hsT[128 * 36];  // [h][32 rows], stride 36

    int b0 = blockIdx.x * 32;
    int d  = blockIdx.y;
    int tt = blockIdx.z;
    int t  = tt + 3;

    const float* src = d_htraj + (((size_t)t * D_ + d) * B_ + b0) * H_;
    for (int i = threadIdx.x; i < 32 * 128; i += 288) {
        int r = i >> 7, hh = i & 127;
        hsT[hh * 36 + r] = src[r * 128 + hh];
    }
    __syncthreads();

    int cg = threadIdx.x >> 2;       // 0..71, cols cg*4..cg*4+3
    int rg = threadIdx.x & 3;        // rows rg*8..rg*8+7
    if (cg < 66) {
        int c0 = cg * 4;
        u64 acc[16];                 // [col][rowpair]
#pragma unroll
        for (int i = 0; i < 16; i++) acc[i] = 0ull;

        const float* hb = &hsT[rg * 8];
#pragma unroll 4
        for (int k = 0; k < H_; k++) {
            float4 w4 = __ldg((const float4*)&d_qkT2[k * QKC + c0]);
            const ulonglong2* hp = (const ulonglong2*)&hb[k * 36];
            ulonglong2 p0 = hp[0], p1 = hp[1];
            u64 w0 = pack2(w4.x), w1 = pack2(w4.y), w2 = pack2(w4.z), w3 = pack2(w4.w);
            ffma2(acc[0],  p0.x, w0); ffma2(acc[1],  p0.y, w0);
            ffma2(acc[2],  p1.x, w0); ffma2(acc[3],  p1.y, w0);
            ffma2(acc[4],  p0.x, w1); ffma2(acc[5],  p0.y, w1);
            ffma2(acc[6],  p1.x, w1); ffma2(acc[7],  p1.y, w1);
            ffma2(acc[8],  p0.x, w2); ffma2(acc[9],  p0.y, w2);
            ffma2(acc[10], p1.x, w2); ffma2(acc[11], p1.y, w2);
            ffma2(acc[12], p0.x, w3); ffma2(acc[13], p0.y, w3);
            ffma2(acc[14], p1.x, w3); ffma2(acc[15], p1.y, w3);
        }

        float* dst = d_qkbuf + (((size_t)tt * D_ + d) * B_ + b0 + rg * 8) * QKC;
#pragma unroll
        for (int rp = 0; rp < 4; rp++) {
            float v0l, v0h, v1l, v1h, v2l, v2h, v3l, v3h;
            unpack2(acc[rp],      v0l, v0h);
            unpack2(acc[4 + rp],  v1l, v1h);
            unpack2(acc[8 + rp],  v2l, v2h);
            unpack2(acc[12 + rp], v3l, v3h);
            *(float4*)&dst[(size_t)(2 * rp) * QKC + c0]     = make_float4(v0l, v1l, v2l, v3l);
            *(float4*)&dst[(size_t)(2 * rp + 1) * QKC + c0] = make_float4(v0h, v1h, v2h, v3h);
        }
    }
}

// ---------------- phase 2b: scores + softmax + threshold + prediction ----------------
__global__ __launch_bounds__(128) void phase2b(const float* __restrict__ b_p,
                                               float* __restrict__ out) {
    __shared__ __align__(16) float qk[32 * 266];
    __shared__ float wsum[4];

    int b  = blockIdx.x;
    int tt = blockIdx.y;

    const float* src = d_qkbuf + (((size_t)tt * D_) * B_ + b) * QKC;
    for (int d = 0; d < 32; d++) {
        const float* row = src + (size_t)d * B_ * QKC;
        for (int cc = threadIdx.x; cc < QKC; cc += 128) qk[d * 266 + cc] = row[cc];
    }
    __syncthreads();

    int head = threadIdx.x >> 5, j = threadIdx.x & 31;

    u64 kk[16];
    const float* krow = &qk[j * 266 + 128 + head * 32];
#pragma unroll
    for (int i2 = 0; i2 < 16; i2++) {
        float2 f = *(const float2*)&krow[2 * i2];
        kk[i2] = pack2f(f.x, f.y);
    }
    float vgj = qk[j * 266 + 256 + head];

    float acc = 0.f;
    for (int i = 0; i < 32; i++) {
        const float2* qrow = (const float2*)&qk[i * 266 + head * 32];
        u64 sacc = 0ull;
#pragma unroll
        for (int i2 = 0; i2 < 16; i2++) {
            float2 f = qrow[i2];
            ffma2(sacc, pack2f(f.x, f.y), kk[i2]);
        }
        float lo, hi;
        unpack2(sacc, lo, hi);
        float s = (lo + hi) * SCALE_ATTN;

        float m = s;
#pragma unroll
        for (int off = 16; off; off >>= 1) m = fmaxf(m, __shfl_xor_sync(0xffffffffu, m, off));
        float e = fexp2a((s - m) * LOG2E_F);
        float ssum = e;
#pragma unroll
        for (int off = 16; off; off >>= 1) ssum += __shfl_xor_sync(0xffffffffu, ssum, off);
        float p = e * frcpa(ssum);
        float contrib = (p >= 0.01f) ? p * vgj : 0.f;
#pragma unroll
        for (int off = 16; off; off >>= 1) contrib += __shfl_xor_sync(0xffffffffu, contrib, off);
        acc += contrib;
    }
    if (j == 0) wsum[head] = acc;
    __syncthreads();
    if (threadIdx.x == 0)
        out[b * TOUT + tt] = (wsum[0] + wsum[1] + wsum[2] + wsum[3]) * (1.f / 32.f) + b_p[0];
}

// ---------------- launch ----------------
extern "C" void kernel_launch(void* const* d_in, const int* in_sizes, int n_in,
                              void* d_out, int out_size) {
    const float* x   = (const float*)d_in[0];
    const float* Uj  = (const float*)d_in[1];
    const float* Ui  = (const float*)d_in[2];
    const float* Uf  = (const float*)d_in[3];
    const float* Uo  = (const float*)d_in[4];
    const float* Wj  = (const float*)d_in[5];
    const float* Wi  = (const float*)d_in[6];
    const float* Wf  = (const float*)d_in[7];
    const float* Wo  = (const float*)d_in[8];
    const float* Bj  = (const float*)d_in[9];
    const float* Bi  = (const float*)d_in[10];
    const float* Bf  = (const float*)d_in[11];
    const float* Bo  = (const float*)d_in[12];
    // d_in[13..24] dead code
    const float* qkv_w    = (const float*)d_in[25];
    const float* out_w    = (const float*)d_in[26];
    const float* h_proj_w = (const float*)d_in[27];
    const float* w_p      = (const float*)d_in[28];
    const float* b_p      = (const float*)d_in[29];
    float* out = (float*)d_out;

    prep_wcat<<<(D_ * H_ * NG + 255) / 256, 256>>>(Wj, Wi, Wf, Wo);
    prep_ub<<<(D_ * NG + 255) / 256, 256>>>(Uj, Ui, Uf, Uo, Bj, Bi, Bf, Bo);
    prep_attn<<<1, 128>>>(qkv_w, out_w, h_proj_w, w_p);

    int smem1_bytes = SM1_TOTAL * 4;   // ~181 KB
    cudaFuncSetAttribute(phase1, cudaFuncAttributeMaxDynamicSharedMemorySize, smem1_bytes);
    phase1<<<128, 512, smem1_bytes>>>(x);

    dim3 g2a(2, 32, 252);
    phase2a<<<g2a, 288>>>();

    dim3 g2b(B_, TOUT);
    phase2b<<<g2b, 128>>>(b_p, out);
}

// round 9
// speedup vs baseline: 2.8410x; 1.3520x over previous
#include <cuda_runtime.h>
#include <math.h>

// Problem constants
#define D_    32
#define H_    128
#define B_    64
#define T_    256
#define NSTEP 255
#define TOUT  252
#define NG    512          // 4 gates * 128
#define QKC   264          // 256 q/k cols + 4 vg cols + 4 pad
#define KREG  40           // weight k-slices in registers (float4 per k)
#define KSM   88           // weight k-slices in shared memory
#define HTS   20           // hT row stride (floats), 16B-aligned
#define SCALE_ATTN 0.17677669529663688f
#define LOG2E_F 1.4426950408889634f

typedef unsigned long long u64;

// ---------------- device scratch ----------------
__device__ float d_Wcat2[D_ * H_ * H_ * 4];               // [d][k][h][gate j,i,f,o]
__device__ float d_Ucat2[D_ * H_ * 4];                    // [d][h][gate]
__device__ float d_Bcat2[D_ * H_ * 4];                    // [d][h][gate]
__device__ float d_qkT2[H_ * QKC];                        // [m][c]
__device__ float d_htraj[(size_t)NSTEP * D_ * B_ * H_];   // [t][d][b][h]
__device__ float d_qkbuf[(size_t)TOUT * D_ * B_ * QKC];   // [tt][d][b][c]

// ---------------- fast math helpers ----------------
__device__ __forceinline__ float fexp2a(float x) {
    float r; asm("ex2.approx.ftz.f32 %0, %1;" : "=f"(r) : "f"(x)); return r;
}
__device__ __forceinline__ float frcpa(float x) {
    float r; asm("rcp.approx.ftz.f32 %0, %1;" : "=f"(r) : "f"(x)); return r;
}
__device__ __forceinline__ float fsigmoid(float x) {
    return frcpa(1.f + fexp2a(-x * LOG2E_F));
}
__device__ __forceinline__ float ftanh(float x) {
    return fmaf(-2.f, frcpa(1.f + fexp2a(x * (2.f * LOG2E_F))), 1.f);
}
__device__ __forceinline__ void ffma2(u64& d, u64 a, u64 b) {
    asm("fma.rn.f32x2 %0, %1, %2, %0;" : "+l"(d) : "l"(a), "l"(b));
}
__device__ __forceinline__ u64 pack2(float w) {
    u64 r; asm("mov.b64 %0, {%1, %1};" : "=l"(r) : "f"(w)); return r;
}
__device__ __forceinline__ u64 pack2f(float lo, float hi) {
    u64 r; asm("mov.b64 %0, {%1, %2};" : "=l"(r) : "f"(lo), "f"(hi)); return r;
}
__device__ __forceinline__ void unpack2(u64 v, float& lo, float& hi) {
    asm("mov.b64 {%0, %1}, %2;" : "=f"(lo), "=f"(hi) : "l"(v));
}

// ---------------- prep kernels ----------------
__global__ void prep_wcat2(const float* __restrict__ Wj, const float* __restrict__ Wi,
                           const float* __restrict__ Wf, const float* __restrict__ Wo) {
    int idx = blockIdx.x * 256 + threadIdx.x;            // total 32*128*128*4
    if (idx >= D_ * H_ * H_ * 4) return;
    int g = idx & 3, h = (idx >> 2) & 127, k = (idx >> 9) & 127, d = idx >> 16;
    const float* W = (g == 0) ? Wj : (g == 1) ? Wi : (g == 2) ? Wf : Wo;
    d_Wcat2[idx] = W[(d * H_ + k) * H_ + h];
}

__global__ void prep_ub2(const float* __restrict__ Uj, const float* __restrict__ Ui,
                         const float* __restrict__ Uf, const float* __restrict__ Uo,
                         const float* __restrict__ Bj, const float* __restrict__ Bi,
                         const float* __restrict__ Bf, const float* __restrict__ Bo) {
    int idx = blockIdx.x * 256 + threadIdx.x;            // total 32*128*4
    if (idx >= D_ * H_ * 4) return;
    int g = idx & 3, h = (idx >> 2) & 127, d = idx >> 9;
    const float* U = (g == 0) ? Uj : (g == 1) ? Ui : (g == 2) ? Uf : Uo;
    const float* Bp = (g == 0) ? Bj : (g == 1) ? Bi : (g == 2) ? Bf : Bo;
    d_Ucat2[idx] = U[d * H_ + h];
    d_Bcat2[idx] = Bp[d * H_ + h];
}

__global__ void prep_attn(const float* __restrict__ qkv_w, const float* __restrict__ out_w,
                          const float* __restrict__ h_proj_w, const float* __restrict__ w_p) {
    __shared__ float g_s[128];
    __shared__ float g2_s[128];
    int tid = threadIdx.x;  // = m
    float acc = 0.f;
    for (int n = 0; n < 128; n++) acc += h_proj_w[n * 128 + tid] * w_p[n];
    g_s[tid] = acc;
    __syncthreads();
    acc = 0.f;
    for (int hh = 0; hh < 128; hh++) acc += out_w[hh * 128 + tid] * g_s[hh];
    g2_s[tid] = acc;
    __syncthreads();
    for (int c = 0; c < 256; c++) d_qkT2[tid * QKC + c] = qkv_w[c * 128 + tid];
    for (int head = 0; head < 4; head++) {
        float a = 0.f;
        for (int hd = 0; hd < 32; hd++)
            a += qkv_w[(256 + head * 32 + hd) * 128 + tid] * g2_s[head * 32 + hd];
        d_qkT2[tid * QKC + 256 + head] = a;
    }
    for (int c = 260; c < QKC; c++) d_qkT2[tid * QKC + c] = 0.f;
}

// ---------------- phase 1: 255-step recurrence ----------------
// 128 CTAs = 32 d * 4 batch-tiles of 16.  256 threads: h = tid&127, bg = tid>>7.
// Thread owns (h, 8 batches, ALL 4 gates): gate-local epilogue, c in registers,
// NO pre-activation exchange, ONE __syncthreads per step.
// Weights resident: KREG k-slices in registers (float4) + KSM in smem.
// Dynamic smem (floats):
//   wsm   [0, KSM*512)  : [kk][h][gate]          176 KB
//   hT    [.., +2*128*HTS) : double-buffered h    20 KB
//   xsall [.., +NSTEP*16)  : all x values          16 KB
#define SM1_WSM 0
#define SM1_HT  (KSM * NG)
#define SM1_XS  (SM1_HT + 2 * H_ * HTS)
#define SM1_TOTAL (SM1_XS + NSTEP * 16)

#define FMA16(P0, P1, WJ, WI, WF, WO) \
    ffma2(aj[0], P0.x, WJ); ffma2(aj[1], P0.y, WJ); ffma2(aj[2], P1.x, WJ); ffma2(aj[3], P1.y, WJ); \
    ffma2(ai[0], P0.x, WI); ffma2(ai[1], P0.y, WI); ffma2(ai[2], P1.x, WI); ffma2(ai[3], P1.y, WI); \
    ffma2(af[0], P0.x, WF); ffma2(af[1], P0.y, WF); ffma2(af[2], P1.x, WF); ffma2(af[3], P1.y, WF); \
    ffma2(ao[0], P0.x, WO); ffma2(ao[1], P0.y, WO); ffma2(ao[2], P1.x, WO); ffma2(ao[3], P1.y, WO)

__global__ __launch_bounds__(256) void phase1(const float* __restrict__ x) {
    extern __shared__ __align__(16) float smem1[];
    float* wsm   = smem1 + SM1_WSM;
    float* hT    = smem1 + SM1_HT;
    float* xsall = smem1 + SM1_XS;

    int d  = blockIdx.x & 31;
    int bt = blockIdx.x >> 5;
    int b0 = bt * 16;
    int tid = threadIdx.x;
    int h  = tid & 127;
    int bg = tid >> 7;                 // batch group: batches bg*8 .. bg*8+7

    const float* Wd = d_Wcat2 + (size_t)d * H_ * H_ * 4;   // [k][h][gate]

    // register-resident weights for this thread's h (first KREG k-slices)
    float4 wreg[KREG];
#pragma unroll
    for (int k = 0; k < KREG; k++) wreg[k] = *(const float4*)&Wd[(k * H_ + h) * 4];
    // smem-resident weights (remaining KSM k-slices), coalesced copy
    for (int i = tid; i < KSM * NG; i += 256) wsm[i] = Wd[KREG * NG + i];
    // all x inputs for this (d, batch-tile): 255 steps * 16 batches
    for (int i = tid; i < NSTEP * 16; i += 256) {
        int t = i >> 4, bb = i & 15;
        xsall[i] = x[((b0 + bb) * T_ + t) * D_ + d];
    }
    for (int i = tid; i < 2 * H_ * HTS; i += 256) hT[i] = 0.f;

    float4 u4    = *(const float4*)&d_Ucat2[(d * H_ + h) * 4];
    float4 bias4 = *(const float4*)&d_Bcat2[(d * H_ + h) * 4];
    float creg[8] = {0.f, 0.f, 0.f, 0.f, 0.f, 0.f, 0.f, 0.f};
    __syncthreads();

    for (int t = 0; t < NSTEP; t++) {
        int cur = t & 1, nxt = cur ^ 1;
        const float* hc = &hT[cur * H_ * HTS + bg * 8];

        u64 aj[4] = {0ull,0ull,0ull,0ull};
        u64 ai[4] = {0ull,0ull,0ull,0ull};
        u64 af[4] = {0ull,0ull,0ull,0ull};
        u64 ao[4] = {0ull,0ull,0ull,0ull};

#pragma unroll
        for (int k = 0; k < KREG; k++) {
            u64 wj = pack2(wreg[k].x), wi = pack2(wreg[k].y);
            u64 wf = pack2(wreg[k].z), wo = pack2(wreg[k].w);
            const ulonglong2* hp = (const ulonglong2*)&hc[k * HTS];
            ulonglong2 p0 = hp[0], p1 = hp[1];
            FMA16(p0, p1, wj, wi, wf, wo);
        }
#pragma unroll 8
        for (int kk = 0; kk < KSM; kk++) {
            float4 w4 = *(const float4*)&wsm[kk * NG + h * 4];
            u64 wj = pack2(w4.x), wi = pack2(w4.y), wf = pack2(w4.z), wo = pack2(w4.w);
            const ulonglong2* hp = (const ulonglong2*)&hc[(KREG + kk) * HTS];
            ulonglong2 p0 = hp[0], p1 = hp[1];
            FMA16(p0, p1, wj, wi, wf, wo);
        }

        const float* xs = &xsall[t * 16 + bg * 8];
        float* hw = &hT[nxt * H_ * HTS + h * HTS + bg * 8];
        size_t tb = (((size_t)t * D_ + d) * B_ + b0 + bg * 8) * H_ + h;
#pragma unroll
        for (int p = 0; p < 4; p++) {
            float j0, j1, i0, i1, f0, f1, o0, o1;
            unpack2(aj[p], j0, j1);
            unpack2(ai[p], i0, i1);
            unpack2(af[p], f0, f1);
            unpack2(ao[p], o0, o1);
            {
                float xv = xs[2 * p];
                float jj = ftanh(fmaf(xv, u4.x, j0 + bias4.x));
                float ii = fsigmoid(fmaf(xv, u4.y, i0 + bias4.y));
                float ff = fsigmoid(fmaf(xv, u4.z, f0 + bias4.z));
                float oo = fsigmoid(fmaf(xv, u4.w, o0 + bias4.w));
                creg[2 * p] = fmaf(creg[2 * p], ff, ii * jj);
                float hv = oo * ftanh(creg[2 * p]);
                hw[2 * p] = hv;
                d_htraj[tb + (size_t)(2 * p) * H_] = hv;
            }
            {
                float xv = xs[2 * p + 1];
                float jj = ftanh(fmaf(xv, u4.x, j1 + bias4.x));
                float ii = fsigmoid(fmaf(xv, u4.y, i1 + bias4.y));
                float ff = fsigmoid(fmaf(xv, u4.z, f1 + bias4.z));
                float oo = fsigmoid(fmaf(xv, u4.w, o1 + bias4.w));
                creg[2 * p + 1] = fmaf(creg[2 * p + 1], ff, ii * jj);
                float hv = oo * ftanh(creg[2 * p + 1]);
                hw[2 * p + 1] = hv;
                d_htraj[tb + (size_t)(2 * p + 1) * H_] = hv;
            }
        }
        __syncthreads();   // hT[nxt] complete before it becomes cur
    }
}

// ---------------- phase 2a: batched q/k/vg projection (proven R8 version) ----------------
__global__ __launch_bounds__(288) void phase2a() {
    __shared__ __align__(16) float hsT[128 * 36];  // [h][32 rows], stride 36

    int b0 = blockIdx.x * 32;
    int d  = blockIdx.y;
    int tt = blockIdx.z;
    int t  = tt + 3;

    const float* src = d_htraj + (((size_t)t * D_ + d) * B_ + b0) * H_;
    for (int i = threadIdx.x; i < 32 * 128; i += 288) {
        int r = i >> 7, hh = i & 127;
        hsT[hh * 36 + r] = src[r * 128 + hh];
    }
    __syncthreads();

    int cg = threadIdx.x >> 2;       // 0..71, cols cg*4..cg*4+3
    int rg = threadIdx.x & 3;        // rows rg*8..rg*8+7
    if (cg < 66) {
        int c0 = cg * 4;
        u64 acc[16];                 // [col][rowpair]
#pragma unroll
        for (int i = 0; i < 16; i++) acc[i] = 0ull;

        const float* hb = &hsT[rg * 8];
#pragma unroll 4
        for (int k = 0; k < H_; k++) {
            float4 w4 = __ldg((const float4*)&d_qkT2[k * QKC + c0]);
            const ulonglong2* hp = (const ulonglong2*)&hb[k * 36];
            ulonglong2 p0 = hp[0], p1 = hp[1];
            u64 w0 = pack2(w4.x), w1 = pack2(w4.y), w2 = pack2(w4.z), w3 = pack2(w4.w);
            ffma2(acc[0],  p0.x, w0); ffma2(acc[1],  p0.y, w0);
            ffma2(acc[2],  p1.x, w0); ffma2(acc[3],  p1.y, w0);
            ffma2(acc[4],  p0.x, w1); ffma2(acc[5],  p0.y, w1);
            ffma2(acc[6],  p1.x, w1); ffma2(acc[7],  p1.y, w1);
            ffma2(acc[8],  p0.x, w2); ffma2(acc[9],  p0.y, w2);
            ffma2(acc[10], p1.x, w2); ffma2(acc[11], p1.y, w2);
            ffma2(acc[12], p0.x, w3); ffma2(acc[13], p0.y, w3);
            ffma2(acc[14], p1.x, w3); ffma2(acc[15], p1.y, w3);
        }

        float* dst = d_qkbuf + (((size_t)tt * D_ + d) * B_ + b0 + rg * 8) * QKC;
#pragma unroll
        for (int rp = 0; rp < 4; rp++) {
            float v0l, v0h, v1l, v1h, v2l, v2h, v3l, v3h;
            unpack2(acc[rp],      v0l, v0h);
            unpack2(acc[4 + rp],  v1l, v1h);
            unpack2(acc[8 + rp],  v2l, v2h);
            unpack2(acc[12 + rp], v3l, v3h);
            *(float4*)&dst[(size_t)(2 * rp) * QKC + c0]     = make_float4(v0l, v1l, v2l, v3l);
            *(float4*)&dst[(size_t)(2 * rp + 1) * QKC + c0] = make_float4(v0h, v1h, v2h, v3h);
        }
    }
}

// ---------------- phase 2b: scores + softmax + threshold + prediction ----------------
__global__ __launch_bounds__(128) void phase2b(const float* __restrict__ b_p,
                                               float* __restrict__ out) {
    __shared__ __align__(16) float qk[32 * 266];
    __shared__ float wsum[4];

    int b  = blockIdx.x;
    int tt = blockIdx.y;

    const float* src = d_qkbuf + (((size_t)tt * D_) * B_ + b) * QKC;
    for (int d = 0; d < 32; d++) {
        const float* row = src + (size_t)d * B_ * QKC;
        for (int cc = threadIdx.x; cc < QKC; cc += 128) qk[d * 266 + cc] = row[cc];
    }
    __syncthreads();

    int head = threadIdx.x >> 5, j = threadIdx.x & 31;

    u64 kk[16];
    const float* krow = &qk[j * 266 + 128 + head * 32];
#pragma unroll
    for (int i2 = 0; i2 < 16; i2++) {
        float2 f = *(const float2*)&krow[2 * i2];
        kk[i2] = pack2f(f.x, f.y);
    }
    float vgj = qk[j * 266 + 256 + head];

    float acc = 0.f;
    for (int i = 0; i < 32; i++) {
        const float2* qrow = (const float2*)&qk[i * 266 + head * 32];
        u64 sacc = 0ull;
#pragma unroll
        for (int i2 = 0; i2 < 16; i2++) {
            float2 f = qrow[i2];
            ffma2(sacc, pack2f(f.x, f.y), kk[i2]);
        }
        float lo, hi;
        unpack2(sacc, lo, hi);
        float s = (lo + hi) * SCALE_ATTN;

        float m = s;
#pragma unroll
        for (int off = 16; off; off >>= 1) m = fmaxf(m, __shfl_xor_sync(0xffffffffu, m, off));
        float e = fexp2a((s - m) * LOG2E_F);
        float ssum = e;
#pragma unroll
        for (int off = 16; off; off >>= 1) ssum += __shfl_xor_sync(0xffffffffu, ssum, off);
        float p = e * frcpa(ssum);
        float contrib = (p >= 0.01f) ? p * vgj : 0.f;
#pragma unroll
        for (int off = 16; off; off >>= 1) contrib += __shfl_xor_sync(0xffffffffu, contrib, off);
        acc += contrib;
    }
    if (j == 0) wsum[head] = acc;
    __syncthreads();
    if (threadIdx.x == 0)
        out[b * TOUT + tt] = (wsum[0] + wsum[1] + wsum[2] + wsum[3]) * (1.f / 32.f) + b_p[0];
}

// ---------------- launch ----------------
extern "C" void kernel_launch(void* const* d_in, const int* in_sizes, int n_in,
                              void* d_out, int out_size) {
    const float* x   = (const float*)d_in[0];
    const float* Uj  = (const float*)d_in[1];
    const float* Ui  = (const float*)d_in[2];
    const float* Uf  = (const float*)d_in[3];
    const float* Uo  = (const float*)d_in[4];
    const float* Wj  = (const float*)d_in[5];
    const float* Wi  = (const float*)d_in[6];
    const float* Wf  = (const float*)d_in[7];
    const float* Wo  = (const float*)d_in[8];
    const float* Bj  = (const float*)d_in[9];
    const float* Bi  = (const float*)d_in[10];
    const float* Bf  = (const float*)d_in[11];
    const float* Bo  = (const float*)d_in[12];
    // d_in[13..24] dead code
    const float* qkv_w    = (const float*)d_in[25];
    const float* out_w    = (const float*)d_in[26];
    const float* h_proj_w = (const float*)d_in[27];
    const float* w_p      = (const float*)d_in[28];
    const float* b_p      = (const float*)d_in[29];
    float* out = (float*)d_out;

    prep_wcat2<<<(D_ * H_ * H_ * 4 + 255) / 256, 256>>>(Wj, Wi, Wf, Wo);
    prep_ub2<<<(D_ * H_ * 4 + 255) / 256, 256>>>(Uj, Ui, Uf, Uo, Bj, Bi, Bf, Bo);
    prep_attn<<<1, 128>>>(qkv_w, out_w, h_proj_w, w_p);

    int smem1_bytes = SM1_TOTAL * 4;   // ~212 KB
    cudaFuncSetAttribute(phase1, cudaFuncAttributeMaxDynamicSharedMemorySize, smem1_bytes);
    phase1<<<128, 256, smem1_bytes>>>(x);

    dim3 g2a(2, 32, 252);
    phase2a<<<g2a, 288>>>();

    dim3 g2b(B_, TOUT);
    phase2b<<<g2b, 128>>>(b_p, out);
}

// round 10
// speedup vs baseline: 2.8575x; 1.0058x over previous
#include <cuda_runtime.h>
#include <math.h>

// Problem constants
#define D_    32
#define H_    128
#define B_    64
#define T_    256
#define NSTEP 255
#define TOUT  252
#define NG    512          // 4 gates * 128
#define QKC   264          // 256 q/k cols + 4 vg cols + 4 pad
#define KREG  40           // weight k-slices in registers (float4 per k)
#define KSM   88           // weight k-slices in shared memory
#define HTS   20           // hT row stride (floats), 16B-aligned
#define QKS   268          // phase2b smem row stride (16B-aligned)
#define SCALE_ATTN 0.17677669529663688f
#define LOG2E_F 1.4426950408889634f

typedef unsigned long long u64;

// ---------------- device scratch ----------------
__device__ float d_Wcat2[D_ * H_ * H_ * 4];               // [d][k][h][gate j,i,f,o]
__device__ float d_Ucat2[D_ * H_ * 4];                    // [d][h][gate]
__device__ float d_Bcat2[D_ * H_ * 4];                    // [d][h][gate]
__device__ float d_qkT2[H_ * QKC];                        // [m][c]
__device__ float d_htraj[(size_t)NSTEP * D_ * B_ * H_];   // [t][d][b][h]
__device__ float d_qkbuf[(size_t)TOUT * D_ * B_ * QKC];   // [tt][d][b][c]

// ---------------- fast math helpers ----------------
__device__ __forceinline__ float fexp2a(float x) {
    float r; asm("ex2.approx.ftz.f32 %0, %1;" : "=f"(r) : "f"(x)); return r;
}
__device__ __forceinline__ float frcpa(float x) {
    float r; asm("rcp.approx.ftz.f32 %0, %1;" : "=f"(r) : "f"(x)); return r;
}
__device__ __forceinline__ float fsigmoid(float x) {
    return frcpa(1.f + fexp2a(-x * LOG2E_F));
}
__device__ __forceinline__ float ftanh(float x) {
    return fmaf(-2.f, frcpa(1.f + fexp2a(x * (2.f * LOG2E_F))), 1.f);
}
__device__ __forceinline__ void ffma2(u64& d, u64 a, u64 b) {
    asm("fma.rn.f32x2 %0, %1, %2, %0;" : "+l"(d) : "l"(a), "l"(b));
}
__device__ __forceinline__ u64 pack2(float w) {
    u64 r; asm("mov.b64 %0, {%1, %1};" : "=l"(r) : "f"(w)); return r;
}
__device__ __forceinline__ u64 pack2f(float lo, float hi) {
    u64 r; asm("mov.b64 %0, {%1, %2};" : "=l"(r) : "f"(lo), "f"(hi)); return r;
}
__device__ __forceinline__ void unpack2(u64 v, float& lo, float& hi) {
    asm("mov.b64 {%0, %1}, %2;" : "=f"(lo), "=f"(hi) : "l"(v));
}

// ---------------- prep kernels ----------------
__global__ void prep_wcat2(const float* __restrict__ Wj, const float* __restrict__ Wi,
                           const float* __restrict__ Wf, const float* __restrict__ Wo) {
    int idx = blockIdx.x * 256 + threadIdx.x;            // total 32*128*128*4
    if (idx >= D_ * H_ * H_ * 4) return;
    int g = idx & 3, h = (idx >> 2) & 127, k = (idx >> 9) & 127, d = idx >> 16;
    const float* W = (g == 0) ? Wj : (g == 1) ? Wi : (g == 2) ? Wf : Wo;
    d_Wcat2[idx] = W[(d * H_ + k) * H_ + h];
}

__global__ void prep_ub2(const float* __restrict__ Uj, const float* __restrict__ Ui,
                         const float* __restrict__ Uf, const float* __restrict__ Uo,
                         const float* __restrict__ Bj, const float* __restrict__ Bi,
                         const float* __restrict__ Bf, const float* __restrict__ Bo) {
    int idx = blockIdx.x * 256 + threadIdx.x;            // total 32*128*4
    if (idx >= D_ * H_ * 4) return;
    int g = idx & 3, h = (idx >> 2) & 127, d = idx >> 9;
    const float* U = (g == 0) ? Uj : (g == 1) ? Ui : (g == 2) ? Uf : Uo;
    const float* Bp = (g == 0) ? Bj : (g == 1) ? Bi : (g == 2) ? Bf : Bo;
    d_Ucat2[idx] = U[d * H_ + h];
    d_Bcat2[idx] = Bp[d * H_ + h];
}

__global__ void prep_attn(const float* __restrict__ qkv_w, const float* __restrict__ out_w,
                          const float* __restrict__ h_proj_w, const float* __restrict__ w_p) {
    __shared__ float g_s[128];
    __shared__ float g2_s[128];
    int tid = threadIdx.x;  // = m
    float acc = 0.f;
    for (int n = 0; n < 128; n++) acc += h_proj_w[n * 128 + tid] * w_p[n];
    g_s[tid] = acc;
    __syncthreads();
    acc = 0.f;
    for (int hh = 0; hh < 128; hh++) acc += out_w[hh * 128 + tid] * g_s[hh];
    g2_s[tid] = acc;
    __syncthreads();
    for (int c = 0; c < 256; c++) d_qkT2[tid * QKC + c] = qkv_w[c * 128 + tid];
    for (int head = 0; head < 4; head++) {
        float a = 0.f;
        for (int hd = 0; hd < 32; hd++)
            a += qkv_w[(256 + head * 32 + hd) * 128 + tid] * g2_s[head * 32 + hd];
        d_qkT2[tid * QKC + 256 + head] = a;
    }
    for (int c = 260; c < QKC; c++) d_qkT2[tid * QKC + c] = 0.f;
}

// ---------------- phase 1: 255-step recurrence (proven R9 version) ----------------
#define SM1_WSM 0
#define SM1_HT  (KSM * NG)
#define SM1_XS  (SM1_HT + 2 * H_ * HTS)
#define SM1_TOTAL (SM1_XS + NSTEP * 16)

#define FMA16(P0, P1, WJ, WI, WF, WO) \
    ffma2(aj[0], P0.x, WJ); ffma2(aj[1], P0.y, WJ); ffma2(aj[2], P1.x, WJ); ffma2(aj[3], P1.y, WJ); \
    ffma2(ai[0], P0.x, WI); ffma2(ai[1], P0.y, WI); ffma2(ai[2], P1.x, WI); ffma2(ai[3], P1.y, WI); \
    ffma2(af[0], P0.x, WF); ffma2(af[1], P0.y, WF); ffma2(af[2], P1.x, WF); ffma2(af[3], P1.y, WF); \
    ffma2(ao[0], P0.x, WO); ffma2(ao[1], P0.y, WO); ffma2(ao[2], P1.x, WO); ffma2(ao[3], P1.y, WO)

__global__ __launch_bounds__(256) void phase1(const float* __restrict__ x) {
    extern __shared__ __align__(16) float smem1[];
    float* wsm   = smem1 + SM1_WSM;
    float* hT    = smem1 + SM1_HT;
    float* xsall = smem1 + SM1_XS;

    int d  = blockIdx.x & 31;
    int bt = blockIdx.x >> 5;
    int b0 = bt * 16;
    int tid = threadIdx.x;
    int h  = tid & 127;
    int bg = tid >> 7;                 // batch group: batches bg*8 .. bg*8+7

    const float* Wd = d_Wcat2 + (size_t)d * H_ * H_ * 4;   // [k][h][gate]

    float4 wreg[KREG];
#pragma unroll
    for (int k = 0; k < KREG; k++) wreg[k] = *(const float4*)&Wd[(k * H_ + h) * 4];
    for (int i = tid; i < KSM * NG; i += 256) wsm[i] = Wd[KREG * NG + i];
    for (int i = tid; i < NSTEP * 16; i += 256) {
        int t = i >> 4, bb = i & 15;
        xsall[i] = x[((b0 + bb) * T_ + t) * D_ + d];
    }
    for (int i = tid; i < 2 * H_ * HTS; i += 256) hT[i] = 0.f;

    float4 u4    = *(const float4*)&d_Ucat2[(d * H_ + h) * 4];
    float4 bias4 = *(const float4*)&d_Bcat2[(d * H_ + h) * 4];
    float creg[8] = {0.f, 0.f, 0.f, 0.f, 0.f, 0.f, 0.f, 0.f};
    __syncthreads();

    for (int t = 0; t < NSTEP; t++) {
        int cur = t & 1, nxt = cur ^ 1;
        const float* hc = &hT[cur * H_ * HTS + bg * 8];

        u64 aj[4] = {0ull,0ull,0ull,0ull};
        u64 ai[4] = {0ull,0ull,0ull,0ull};
        u64 af[4] = {0ull,0ull,0ull,0ull};
        u64 ao[4] = {0ull,0ull,0ull,0ull};

#pragma unroll
        for (int k = 0; k < KREG; k++) {
            u64 wj = pack2(wreg[k].x), wi = pack2(wreg[k].y);
            u64 wf = pack2(wreg[k].z), wo = pack2(wreg[k].w);
            const ulonglong2* hp = (const ulonglong2*)&hc[k * HTS];
            ulonglong2 p0 = hp[0], p1 = hp[1];
            FMA16(p0, p1, wj, wi, wf, wo);
        }
#pragma unroll 8
        for (int kk = 0; kk < KSM; kk++) {
            float4 w4 = *(const float4*)&wsm[kk * NG + h * 4];
            u64 wj = pack2(w4.x), wi = pack2(w4.y), wf = pack2(w4.z), wo = pack2(w4.w);
            const ulonglong2* hp = (const ulonglong2*)&hc[(KREG + kk) * HTS];
            ulonglong2 p0 = hp[0], p1 = hp[1];
            FMA16(p0, p1, wj, wi, wf, wo);
        }

        const float* xs = &xsall[t * 16 + bg * 8];
        float* hw = &hT[nxt * H_ * HTS + h * HTS + bg * 8];
        size_t tb = (((size_t)t * D_ + d) * B_ + b0 + bg * 8) * H_ + h;
#pragma unroll
        for (int p = 0; p < 4; p++) {
            float j0, j1, i0, i1, f0, f1, o0, o1;
            unpack2(aj[p], j0, j1);
            unpack2(ai[p], i0, i1);
            unpack2(af[p], f0, f1);
            unpack2(ao[p], o0, o1);
            {
                float xv = xs[2 * p];
                float jj = ftanh(fmaf(xv, u4.x, j0 + bias4.x));
                float ii = fsigmoid(fmaf(xv, u4.y, i0 + bias4.y));
                float ff = fsigmoid(fmaf(xv, u4.z, f0 + bias4.z));
                float oo = fsigmoid(fmaf(xv, u4.w, o0 + bias4.w));
                creg[2 * p] = fmaf(creg[2 * p], ff, ii * jj);
                float hv = oo * ftanh(creg[2 * p]);
                hw[2 * p] = hv;
                d_htraj[tb + (size_t)(2 * p) * H_] = hv;
            }
            {
                float xv = xs[2 * p + 1];
                float jj = ftanh(fmaf(xv, u4.x, j1 + bias4.x));
                float ii = fsigmoid(fmaf(xv, u4.y, i1 + bias4.y));
                float ff = fsigmoid(fmaf(xv, u4.z, f1 + bias4.z));
                float oo = fsigmoid(fmaf(xv, u4.w, o1 + bias4.w));
                creg[2 * p + 1] = fmaf(creg[2 * p + 1], ff, ii * jj);
                float hv = oo * ftanh(creg[2 * p + 1]);
                hw[2 * p + 1] = hv;
                d_htraj[tb + (size_t)(2 * p + 1) * H_] = hv;
            }
        }
        __syncthreads();   // hT[nxt] complete before it becomes cur
    }
}

// ---------------- phase 2a: batched q/k/vg projection (proven R8 version) ----------------
__global__ __launch_bounds__(288) void phase2a() {
    __shared__ __align__(16) float hsT[128 * 36];  // [h][32 rows], stride 36

    int b0 = blockIdx.x * 32;
    int d  = blockIdx.y;
    int tt = blockIdx.z;
    int t  = tt + 3;

    const float* src = d_htraj + (((size_t)t * D_ + d) * B_ + b0) * H_;
    for (int i = threadIdx.x; i < 32 * 128; i += 288) {
        int r = i >> 7, hh = i & 127;
        hsT[hh * 36 + r] = src[r * 128 + hh];
    }
    __syncthreads();

    int cg = threadIdx.x >> 2;       // 0..71, cols cg*4..cg*4+3
    int rg = threadIdx.x & 3;        // rows rg*8..rg*8+7
    if (cg < 66) {
        int c0 = cg * 4;
        u64 acc[16];                 // [col][rowpair]
#pragma unroll
        for (int i = 0; i < 16; i++) acc[i] = 0ull;

        const float* hb = &hsT[rg * 8];
#pragma unroll 4
        for (int k = 0; k < H_; k++) {
            float4 w4 = __ldg((const float4*)&d_qkT2[k * QKC + c0]);
            const ulonglong2* hp = (const ulonglong2*)&hb[k * 36];
            ulonglong2 p0 = hp[0], p1 = hp[1];
            u64 w0 = pack2(w4.x), w1 = pack2(w4.y), w2 = pack2(w4.z), w3 = pack2(w4.w);
            ffma2(acc[0],  p0.x, w0); ffma2(acc[1],  p0.y, w0);
            ffma2(acc[2],  p1.x, w0); ffma2(acc[3],  p1.y, w0);
            ffma2(acc[4],  p0.x, w1); ffma2(acc[5],  p0.y, w1);
            ffma2(acc[6],  p1.x, w1); ffma2(acc[7],  p1.y, w1);
            ffma2(acc[8],  p0.x, w2); ffma2(acc[9],  p0.y, w2);
            ffma2(acc[10], p1.x, w2); ffma2(acc[11], p1.y, w2);
            ffma2(acc[12], p0.x, w3); ffma2(acc[13], p0.y, w3);
            ffma2(acc[14], p1.x, w3); ffma2(acc[15], p1.y, w3);
        }

        float* dst = d_qkbuf + (((size_t)tt * D_ + d) * B_ + b0 + rg * 8) * QKC;
#pragma unroll
        for (int rp = 0; rp < 4; rp++) {
            float v0l, v0h, v1l, v1h, v2l, v2h, v3l, v3h;
            unpack2(acc[rp],      v0l, v0h);
            unpack2(acc[4 + rp],  v1l, v1h);
            unpack2(acc[8 + rp],  v2l, v2h);
            unpack2(acc[12 + rp], v3l, v3h);
            *(float4*)&dst[(size_t)(2 * rp) * QKC + c0]     = make_float4(v0l, v1l, v2l, v3l);
            *(float4*)&dst[(size_t)(2 * rp + 1) * QKC + c0] = make_float4(v0h, v1h, v2h, v3h);
        }
    }
}

// ---------------- phase 2b: shuffle-free scores + softmax + prediction ----------------
// Grid (b=64, tt=252), 128 threads = 4 warps (head), thread = query row i.
// q_i resident in registers; keys broadcast from smem; all 32 scores in registers;
// softmax + threshold + vg-contraction fully serial per thread; ONE warp reduction at end.
__global__ __launch_bounds__(128) void phase2b(const float* __restrict__ b_p,
                                               float* __restrict__ out) {
    __shared__ __align__(16) float qk[32 * QKS];
    __shared__ float wsum[4];

    int b  = blockIdx.x;
    int tt = blockIdx.y;
    int tid = threadIdx.x;

    const float* src = d_qkbuf + (((size_t)tt * D_) * B_ + b) * QKC;
    for (int d = 0; d < 32; d++) {
        const float* row = src + (size_t)d * B_ * QKC;
        for (int cc = tid; cc < QKC; cc += 128) qk[d * QKS + cc] = row[cc];
    }
    __syncthreads();

    int head = tid >> 5, i = tid & 31;

    // q_i -> registers (16B-aligned: (i*QKS + head*32)*4 is a multiple of 16)
    u64 q[16];
    {
        const ulonglong2* qp = (const ulonglong2*)&qk[i * QKS + head * 32];
#pragma unroll
        for (int i2 = 0; i2 < 8; i2++) {
            ulonglong2 v = qp[i2];
            q[2 * i2]     = v.x;
            q[2 * i2 + 1] = v.y;
        }
    }

    // scores s[j] = q_i . k_j  (k_j broadcast across the warp)
    float s[32];
#pragma unroll
    for (int j = 0; j < 32; j++) {
        const ulonglong2* kp = (const ulonglong2*)&qk[j * QKS + 128 + head * 32];
        u64 acc = 0ull;
#pragma unroll
        for (int i2 = 0; i2 < 8; i2++) {
            ulonglong2 kkv = kp[i2];
            ffma2(acc, q[2 * i2],     kkv.x);
            ffma2(acc, q[2 * i2 + 1], kkv.y);
        }
        float lo, hi;
        unpack2(acc, lo, hi);
        s[j] = (lo + hi) * SCALE_ATTN;
    }

    // softmax over j, serial in registers (tree max for shorter dep chain)
    float m01 = fmaxf(s[0], s[1]);
#pragma unroll
    for (int j = 2; j < 32; j += 2) m01 = fmaxf(m01, fmaxf(s[j], s[j + 1]));
    float ssum = 0.f;
#pragma unroll
    for (int j = 0; j < 32; j++) {
        s[j] = fexp2a((s[j] - m01) * LOG2E_F);
        ssum += s[j];
    }
    float inv = frcpa(ssum);

    // thresholded contraction with vg (vg_j broadcast from smem cols 256..259)
    float contrib = 0.f;
#pragma unroll
    for (int j = 0; j < 32; j++) {
        float p = s[j] * inv;
        float vgj = qk[j * QKS + 256 + head];
        contrib += (p >= 0.01f) ? p * vgj : 0.f;
    }

    // one warp reduction over i, then cross-head sum
#pragma unroll
    for (int off = 16; off; off >>= 1) contrib += __shfl_xor_sync(0xffffffffu, contrib, off);
    if (i == 0) wsum[head] = contrib;
    __syncthreads();
    if (tid == 0)
        out[b * TOUT + tt] = (wsum[0] + wsum[1] + wsum[2] + wsum[3]) * (1.f / 32.f) + b_p[0];
}

// ---------------- launch ----------------
extern "C" void kernel_launch(void* const* d_in, const int* in_sizes, int n_in,
                              void* d_out, int out_size) {
    const float* x   = (const float*)d_in[0];
    const float* Uj  = (const float*)d_in[1];
    const float* Ui  = (const float*)d_in[2];
    const float* Uf  = (const float*)d_in[3];
    const float* Uo  = (const float*)d_in[4];
    const float* Wj  = (const float*)d_in[5];
    const float* Wi  = (const float*)d_in[6];
    const float* Wf  = (const float*)d_in[7];
    const float* Wo  = (const float*)d_in[8];
    const float* Bj  = (const float*)d_in[9];
    const float* Bi  = (const float*)d_in[10];
    const float* Bf  = (const float*)d_in[11];
    const float* Bo  = (const float*)d_in[12];
    // d_in[13..24] dead code
    const float* qkv_w    = (const float*)d_in[25];
    const float* out_w    = (const float*)d_in[26];
    const float* h_proj_w = (const float*)d_in[27];
    const float* w_p      = (const float*)d_in[28];
    const float* b_p      = (const float*)d_in[29];
    float* out = (float*)d_out;

    prep_wcat2<<<(D_ * H_ * H_ * 4 + 255) / 256, 256>>>(Wj, Wi, Wf, Wo);
    prep_ub2<<<(D_ * H_ * 4 + 255) / 256, 256>>>(Uj, Ui, Uf, Uo, Bj, Bi, Bf, Bo);
    prep_attn<<<1, 128>>>(qkv_w, out_w, h_proj_w, w_p);

    int smem1_bytes = SM1_TOTAL * 4;   // ~212 KB
    cudaFuncSetAttribute(phase1, cudaFuncAttributeMaxDynamicSharedMemorySize, smem1_bytes);
    phase1<<<128, 256, smem1_bytes>>>(x);

    dim3 g2a(2, 32, 252);
    phase2a<<<g2a, 288>>>();

    dim3 g2b(B_, TOUT);
    phase2b<<<g2b, 128>>>(b_p, out);
}

// round 11
// speedup vs baseline: 3.2546x; 1.1390x over previous
#include <cuda_runtime.h>
#include <math.h>

// Problem constants
#define D_    32
#define H_    128
#define B_    64
#define T_    256
#define NSTEP 255
#define TOUT  252
#define NG    512          // 4 gates * 128
#define QKC   264          // 256 q/k cols + 4 vg cols + 4 pad
#define KREG  40           // phase1 weight k-slices in registers (float4 per k)
#define KSM   88           // phase1 weight k-slices in shared memory
#define HTS   20           // phase1 hT row stride (floats)
#define PS    268          // merged phase2 projection smem row stride (16B-aligned)
#define SCALE_ATTN 0.17677669529663688f
#define LOG2E_F 1.4426950408889634f

typedef unsigned long long u64;

// ---------------- device scratch ----------------
__device__ float d_Wcat2[D_ * H_ * H_ * 4];               // [d][k][h][gate j,i,f,o]
__device__ float d_Ucat2[D_ * H_ * 4];                    // [d][h][gate]
__device__ float d_Bcat2[D_ * H_ * 4];                    // [d][h][gate]
__device__ float d_qkT2[H_ * QKC];                        // [m][c]
__device__ float d_htraj[(size_t)NSTEP * D_ * B_ * H_];   // [t][d][b][h]

// ---------------- fast math helpers ----------------
__device__ __forceinline__ float fexp2a(float x) {
    float r; asm("ex2.approx.ftz.f32 %0, %1;" : "=f"(r) : "f"(x)); return r;
}
__device__ __forceinline__ float frcpa(float x) {
    float r; asm("rcp.approx.ftz.f32 %0, %1;" : "=f"(r) : "f"(x)); return r;
}
__device__ __forceinline__ float fsigmoid(float x) {
    return frcpa(1.f + fexp2a(-x * LOG2E_F));
}
__device__ __forceinline__ float ftanh(float x) {
    return fmaf(-2.f, frcpa(1.f + fexp2a(x * (2.f * LOG2E_F))), 1.f);
}
__device__ __forceinline__ void ffma2(u64& d, u64 a, u64 b) {
    asm("fma.rn.f32x2 %0, %1, %2, %0;" : "+l"(d) : "l"(a), "l"(b));
}
__device__ __forceinline__ u64 pack2(float w) {
    u64 r; asm("mov.b64 %0, {%1, %1};" : "=l"(r) : "f"(w)); return r;
}
__device__ __forceinline__ void unpack2(u64 v, float& lo, float& hi) {
    asm("mov.b64 {%0, %1}, %2;" : "=f"(lo), "=f"(hi) : "l"(v));
}

// ---------------- prep kernels ----------------
__global__ void prep_wcat2(const float* __restrict__ Wj, const float* __restrict__ Wi,
                           const float* __restrict__ Wf, const float* __restrict__ Wo) {
    int idx = blockIdx.x * 256 + threadIdx.x;            // total 32*128*128*4
    if (idx >= D_ * H_ * H_ * 4) return;
    int g = idx & 3, h = (idx >> 2) & 127, k = (idx >> 9) & 127, d = idx >> 16;
    const float* W = (g == 0) ? Wj : (g == 1) ? Wi : (g == 2) ? Wf : Wo;
    d_Wcat2[idx] = W[(d * H_ + k) * H_ + h];
}

__global__ void prep_ub2(const float* __restrict__ Uj, const float* __restrict__ Ui,
                         const float* __restrict__ Uf, const float* __restrict__ Uo,
                         const float* __restrict__ Bj, const float* __restrict__ Bi,
                         const float* __restrict__ Bf, const float* __restrict__ Bo) {
    int idx = blockIdx.x * 256 + threadIdx.x;            // total 32*128*4
    if (idx >= D_ * H_ * 4) return;
    int g = idx & 3, h = (idx >> 2) & 127, d = idx >> 9;
    const float* U = (g == 0) ? Uj : (g == 1) ? Ui : (g == 2) ? Uf : Uo;
    const float* Bp = (g == 0) ? Bj : (g == 1) ? Bi : (g == 2) ? Bf : Bo;
    d_Ucat2[idx] = U[d * H_ + h];
    d_Bcat2[idx] = Bp[d * H_ + h];
}

__global__ void prep_attn(const float* __restrict__ qkv_w, const float* __restrict__ out_w,
                          const float* __restrict__ h_proj_w, const float* __restrict__ w_p) {
    __shared__ float g_s[128];
    __shared__ float g2_s[128];
    int tid = threadIdx.x;  // = m
    float acc = 0.f;
    for (int n = 0; n < 128; n++) acc += h_proj_w[n * 128 + tid] * w_p[n];
    g_s[tid] = acc;
    __syncthreads();
    acc = 0.f;
    for (int hh = 0; hh < 128; hh++) acc += out_w[hh * 128 + tid] * g_s[hh];
    g2_s[tid] = acc;
    __syncthreads();
    for (int c = 0; c < 256; c++) d_qkT2[tid * QKC + c] = qkv_w[c * 128 + tid];
    for (int head = 0; head < 4; head++) {
        float a = 0.f;
        for (int hd = 0; hd < 32; hd++)
            a += qkv_w[(256 + head * 32 + hd) * 128 + tid] * g2_s[head * 32 + hd];
        d_qkT2[tid * QKC + 256 + head] = a;
    }
    for (int c = 260; c < QKC; c++) d_qkT2[tid * QKC + c] = 0.f;
}

// ---------------- phase 1: 255-step recurrence (proven R9 version, unchanged) ----------------
#define SM1_WSM 0
#define SM1_HT  (KSM * NG)
#define SM1_XS  (SM1_HT + 2 * H_ * HTS)
#define SM1_TOTAL (SM1_XS + NSTEP * 16)

#define FMA16(P0, P1, WJ, WI, WF, WO) \
    ffma2(aj[0], P0.x, WJ); ffma2(aj[1], P0.y, WJ); ffma2(aj[2], P1.x, WJ); ffma2(aj[3], P1.y, WJ); \
    ffma2(ai[0], P0.x, WI); ffma2(ai[1], P0.y, WI); ffma2(ai[2], P1.x, WI); ffma2(ai[3], P1.y, WI); \
    ffma2(af[0], P0.x, WF); ffma2(af[1], P0.y, WF); ffma2(af[2], P1.x, WF); ffma2(af[3], P1.y, WF); \
    ffma2(ao[0], P0.x, WO); ffma2(ao[1], P0.y, WO); ffma2(ao[2], P1.x, WO); ffma2(ao[3], P1.y, WO)

__global__ __launch_bounds__(256) void phase1(const float* __restrict__ x) {
    extern __shared__ __align__(16) float smem1[];
    float* wsm   = smem1 + SM1_WSM;
    float* hT    = smem1 + SM1_HT;
    float* xsall = smem1 + SM1_XS;

    int d  = blockIdx.x & 31;
    int bt = blockIdx.x >> 5;
    int b0 = bt * 16;
    int tid = threadIdx.x;
    int h  = tid & 127;
    int bg = tid >> 7;                 // batch group: batches bg*8 .. bg*8+7

    const float* Wd = d_Wcat2 + (size_t)d * H_ * H_ * 4;   // [k][h][gate]

    float4 wreg[KREG];
#pragma unroll
    for (int k = 0; k < KREG; k++) wreg[k] = *(const float4*)&Wd[(k * H_ + h) * 4];
    for (int i = tid; i < KSM * NG; i += 256) wsm[i] = Wd[KREG * NG + i];
    for (int i = tid; i < NSTEP * 16; i += 256) {
        int t = i >> 4, bb = i & 15;
        xsall[i] = x[((b0 + bb) * T_ + t) * D_ + d];
    }
    for (int i = tid; i < 2 * H_ * HTS; i += 256) hT[i] = 0.f;

    float4 u4    = *(const float4*)&d_Ucat2[(d * H_ + h) * 4];
    float4 bias4 = *(const float4*)&d_Bcat2[(d * H_ + h) * 4];
    float creg[8] = {0.f, 0.f, 0.f, 0.f, 0.f, 0.f, 0.f, 0.f};
    __syncthreads();

    for (int t = 0; t < NSTEP; t++) {
        int cur = t & 1, nxt = cur ^ 1;
        const float* hc = &hT[cur * H_ * HTS + bg * 8];

        u64 aj[4] = {0ull,0ull,0ull,0ull};
        u64 ai[4] = {0ull,0ull,0ull,0ull};
        u64 af[4] = {0ull,0ull,0ull,0ull};
        u64 ao[4] = {0ull,0ull,0ull,0ull};

#pragma unroll
        for (int k = 0; k < KREG; k++) {
            u64 wj = pack2(wreg[k].x), wi = pack2(wreg[k].y);
            u64 wf = pack2(wreg[k].z), wo = pack2(wreg[k].w);
            const ulonglong2* hp = (const ulonglong2*)&hc[k * HTS];
            ulonglong2 p0 = hp[0], p1 = hp[1];
            FMA16(p0, p1, wj, wi, wf, wo);
        }
#pragma unroll 8
        for (int kk = 0; kk < KSM; kk++) {
            float4 w4 = *(const float4*)&wsm[kk * NG + h * 4];
            u64 wj = pack2(w4.x), wi = pack2(w4.y), wf = pack2(w4.z), wo = pack2(w4.w);
            const ulonglong2* hp = (const ulonglong2*)&hc[(KREG + kk) * HTS];
            ulonglong2 p0 = hp[0], p1 = hp[1];
            FMA16(p0, p1, wj, wi, wf, wo);
        }

        const float* xs = &xsall[t * 16 + bg * 8];
        float* hw = &hT[nxt * H_ * HTS + h * HTS + bg * 8];
        size_t tb = (((size_t)t * D_ + d) * B_ + b0 + bg * 8) * H_ + h;
#pragma unroll
        for (int p = 0; p < 4; p++) {
            float j0, j1, i0, i1, f0, f1, o0, o1;
            unpack2(aj[p], j0, j1);
            unpack2(ai[p], i0, i1);
            unpack2(af[p], f0, f1);
            unpack2(ao[p], o0, o1);
            {
                float xv = xs[2 * p];
                float jj = ftanh(fmaf(xv, u4.x, j0 + bias4.x));
                float ii = fsigmoid(fmaf(xv, u4.y, i0 + bias4.y));
                float ff = fsigmoid(fmaf(xv, u4.z, f0 + bias4.z));
                float oo = fsigmoid(fmaf(xv, u4.w, o0 + bias4.w));
                creg[2 * p] = fmaf(creg[2 * p], ff, ii * jj);
                float hv = oo * ftanh(creg[2 * p]);
                hw[2 * p] = hv;
                d_htraj[tb + (size_t)(2 * p) * H_] = hv;
            }
            {
                float xv = xs[2 * p + 1];
                float jj = ftanh(fmaf(xv, u4.x, j1 + bias4.x));
                float ii = fsigmoid(fmaf(xv, u4.y, i1 + bias4.y));
                float ff = fsigmoid(fmaf(xv, u4.z, f1 + bias4.z));
                float oo = fsigmoid(fmaf(xv, u4.w, o1 + bias4.w));
                creg[2 * p + 1] = fmaf(creg[2 * p + 1], ff, ii * jj);
                float hv = oo * ftanh(creg[2 * p + 1]);
                hw[2 * p + 1] = hv;
                d_htraj[tb + (size_t)(2 * p + 1) * H_] = hv;
            }
        }
        __syncthreads();   // hT[nxt] complete before it becomes cur
    }
}

// ---------------- phase 2 (FUSED): projection GEMM -> smem -> attention -> pred ----------------
// Grid (b=64, tt=252), 288 threads. One CTA per (b,t):
//   1. load h slab [32 d][128 m] -> hsT[m][d] (stride 36)
//   2. GEMM (phase2a inner, unchanged): psm[d][c] c<256 q/k, 256..259 vg   (stride PS)
//   3. warps 0-3: register-resident scores+softmax+threshold (R10 epilogue)
// smem: hsT 18.4 KB + psm 34.3 KB ≈ 53 KB -> 4 CTAs/SM.
#define SMF_HST  0
#define SMF_PSM  (128 * 36)
#define SMF_WSUM (SMF_PSM + 32 * PS)
#define SMF_TOTAL (SMF_WSUM + 4)
__global__ __launch_bounds__(288) void phase2(const float* __restrict__ b_p,
                                              float* __restrict__ out) {
    extern __shared__ __align__(16) float smf[];
    float* hsT  = smf + SMF_HST;    // [m][32 d], stride 36
    float* psm  = smf + SMF_PSM;    // [d][PS]
    float* wsum = smf + SMF_WSUM;

    int b  = blockIdx.x;
    int tt = blockIdx.y;
    int t  = tt + 3;
    int tid = threadIdx.x;

    // 1. load h slab: element (d, m) at d_htraj[((t*32+d)*64+b)*128 + m]
    const float* src = d_htraj + (((size_t)t * D_) * B_ + b) * H_;
    for (int i = tid; i < 32 * 128; i += 288) {
        int d = i >> 7, m = i & 127;
        hsT[m * 36 + d] = src[(size_t)d * B_ * H_ + m];
    }
    __syncthreads();

    // 2. projection GEMM: thread = 4 cols x 8 d-rows (proven phase2a inner loop)
    int cg = tid >> 2;               // 0..71, cols cg*4..cg*4+3 (active < 66)
    int rg = tid & 3;                // d-rows rg*8..rg*8+7
    if (cg < 66) {
        int c0 = cg * 4;
        u64 acc[16];
#pragma unroll
        for (int i = 0; i < 16; i++) acc[i] = 0ull;

        const float* hb = &hsT[rg * 8];
#pragma unroll 4
        for (int k = 0; k < H_; k++) {
            float4 w4 = __ldg((const float4*)&d_qkT2[k * QKC + c0]);
            const ulonglong2* hp = (const ulonglong2*)&hb[k * 36];
            ulonglong2 p0 = hp[0], p1 = hp[1];
            u64 w0 = pack2(w4.x), w1 = pack2(w4.y), w2 = pack2(w4.z), w3 = pack2(w4.w);
            ffma2(acc[0],  p0.x, w0); ffma2(acc[1],  p0.y, w0);
            ffma2(acc[2],  p1.x, w0); ffma2(acc[3],  p1.y, w0);
            ffma2(acc[4],  p0.x, w1); ffma2(acc[5],  p0.y, w1);
            ffma2(acc[6],  p1.x, w1); ffma2(acc[7],  p1.y, w1);
            ffma2(acc[8],  p0.x, w2); ffma2(acc[9],  p0.y, w2);
            ffma2(acc[10], p1.x, w2); ffma2(acc[11], p1.y, w2);
            ffma2(acc[12], p0.x, w3); ffma2(acc[13], p0.y, w3);
            ffma2(acc[14], p1.x, w3); ffma2(acc[15], p1.y, w3);
        }

        float* dst = &psm[(rg * 8) * PS + c0];
#pragma unroll
        for (int rp = 0; rp < 4; rp++) {
            float v0l, v0h, v1l, v1h, v2l, v2h, v3l, v3h;
            unpack2(acc[rp],      v0l, v0h);
            unpack2(acc[4 + rp],  v1l, v1h);
            unpack2(acc[8 + rp],  v2l, v2h);
            unpack2(acc[12 + rp], v3l, v3h);
            *(float4*)&dst[(2 * rp) * PS]     = make_float4(v0l, v1l, v2l, v3l);
            *(float4*)&dst[(2 * rp + 1) * PS] = make_float4(v0h, v1h, v2h, v3h);
        }
    }
    __syncthreads();

    // 3. attention epilogue on warps 0-3 (head = warp, thread = query row i)
    if (tid < 128) {
        int head = tid >> 5, i = tid & 31;

        u64 q[16];
        {
            const ulonglong2* qp = (const ulonglong2*)&psm[i * PS + head * 32];
#pragma unroll
            for (int i2 = 0; i2 < 8; i2++) {
                ulonglong2 v = qp[i2];
                q[2 * i2]     = v.x;
                q[2 * i2 + 1] = v.y;
            }
        }

        float s[32];
#pragma unroll
        for (int j = 0; j < 32; j++) {
            const ulonglong2* kp = (const ulonglong2*)&psm[j * PS + 128 + head * 32];
            u64 acc = 0ull;
#pragma unroll
            for (int i2 = 0; i2 < 8; i2++) {
                ulonglong2 kkv = kp[i2];
                ffma2(acc, q[2 * i2],     kkv.x);
                ffma2(acc, q[2 * i2 + 1], kkv.y);
            }
            float lo, hi;
            unpack2(acc, lo, hi);
            s[j] = (lo + hi) * SCALE_ATTN;
        }

        float m01 = fmaxf(s[0], s[1]);
#pragma unroll
        for (int j = 2; j < 32; j += 2) m01 = fmaxf(m01, fmaxf(s[j], s[j + 1]));
        float ssum = 0.f;
#pragma unroll
        for (int j = 0; j < 32; j++) {
            s[j] = fexp2a((s[j] - m01) * LOG2E_F);
            ssum += s[j];
        }
        float inv = frcpa(ssum);

        float contrib = 0.f;
#pragma unroll
        for (int j = 0; j < 32; j++) {
            float p = s[j] * inv;
            float vgj = psm[j * PS + 256 + head];
            contrib += (p >= 0.01f) ? p * vgj : 0.f;
        }

#pragma unroll
        for (int off = 16; off; off >>= 1) contrib += __shfl_xor_sync(0xffffffffu, contrib, off);
        if (i == 0) wsum[head] = contrib;
    }
    __syncthreads();
    if (tid == 0)
        out[b * TOUT + tt] = (wsum[0] + wsum[1] + wsum[2] + wsum[3]) * (1.f / 32.f) + b_p[0];
}

// ---------------- launch ----------------
extern "C" void kernel_launch(void* const* d_in, const int* in_sizes, int n_in,
                              void* d_out, int out_size) {
    const float* x   = (const float*)d_in[0];
    const float* Uj  = (const float*)d_in[1];
    const float* Ui  = (const float*)d_in[2];
    const float* Uf  = (const float*)d_in[3];
    const float* Uo  = (const float*)d_in[4];
    const float* Wj  = (const float*)d_in[5];
    const float* Wi  = (const float*)d_in[6];
    const float* Wf  = (const float*)d_in[7];
    const float* Wo  = (const float*)d_in[8];
    const float* Bj  = (const float*)d_in[9];
    const float* Bi  = (const float*)d_in[10];
    const float* Bf  = (const float*)d_in[11];
    const float* Bo  = (const float*)d_in[12];
    // d_in[13..24] dead code
    const float* qkv_w    = (const float*)d_in[25];
    const float* out_w    = (const float*)d_in[26];
    const float* h_proj_w = (const float*)d_in[27];
    const float* w_p      = (const float*)d_in[28];
    const float* b_p      = (const float*)d_in[29];
    float* out = (float*)d_out;

    prep_wcat2<<<(D_ * H_ * H_ * 4 + 255) / 256, 256>>>(Wj, Wi, Wf, Wo);
    prep_ub2<<<(D_ * H_ * 4 + 255) / 256, 256>>>(Uj, Ui, Uf, Uo, Bj, Bi, Bf, Bo);
    prep_attn<<<1, 128>>>(qkv_w, out_w, h_proj_w, w_p);

    int smem1_bytes = SM1_TOTAL * 4;   // ~212 KB
    cudaFuncSetAttribute(phase1, cudaFuncAttributeMaxDynamicSharedMemorySize, smem1_bytes);
    phase1<<<128, 256, smem1_bytes>>>(x);

    int smf_bytes = SMF_TOTAL * 4;     // ~53 KB
    cudaFuncSetAttribute(phase2, cudaFuncAttributeMaxDynamicSharedMemorySize, smf_bytes);
    dim3 g2(B_, TOUT);
    phase2<<<g2, 288, smf_bytes>>>(b_p, out);
}